// round 2
// baseline (speedup 1.0000x reference)
#include <cuda_runtime.h>

#define B_SZ 65536
#define K_IN 784
#define N_H  1024
#define N_C  10
#define BN_EPS 1e-5f

#define BM 128
#define BN 128
#define BK 16

// ---------------- scratch (device globals; no runtime allocation) ----------
__device__ float g_S1t[K_IN * N_H];           // sign(w1)^T  [k][n]
__device__ float g_alpha1[N_H];
__device__ float g_s2a[N_C * N_H];            // alpha2[c] * sign(w2[c][j])
__device__ float g_d[(size_t)B_SZ * N_H];     // d = x @ sign(w1)^T
__device__ float g_psum[256 * N_H];
__device__ float g_psq [256 * N_H];
__device__ float g_c1[N_H];
__device__ float g_c0[N_H];

// ---------------- packed f32x2 helpers (FFMA2) ------------------------------
__device__ __forceinline__ unsigned long long pk2(float lo, float hi) {
    unsigned long long r;
    asm("mov.b64 %0, {%1, %2};" : "=l"(r) : "f"(lo), "f"(hi));
    return r;
}
__device__ __forceinline__ void fma2(unsigned long long& acc,
                                     unsigned long long a,
                                     unsigned long long b) {
    asm("fma.rn.f32x2 %0, %1, %2, %0;" : "+l"(acc) : "l"(a), "l"(b));
}
__device__ __forceinline__ float2 upk(unsigned long long v) {
    float2 r;
    asm("mov.b64 {%0, %1}, %2;" : "=f"(r.x), "=f"(r.y) : "l"(v));
    return r;
}

__device__ __forceinline__ float signf(float w) {
    return (w > 0.f) ? 1.f : ((w < 0.f) ? -1.f : 0.f);
}

// ---------------- weight prep ------------------------------------------------
__global__ void prep_w1(const float* __restrict__ w1) {
    int n = blockIdx.x;                    // output row of w1  [1024]
    const float* row = w1 + n * K_IN;
    float s = 0.f;
    for (int k = threadIdx.x; k < K_IN; k += 128) {
        float w = row[k];
        s += fabsf(w);
        g_S1t[k * N_H + n] = signf(w);
    }
    __shared__ float red[128];
    red[threadIdx.x] = s;
    __syncthreads();
    for (int st = 64; st > 0; st >>= 1) {
        if (threadIdx.x < st) red[threadIdx.x] += red[threadIdx.x + st];
        __syncthreads();
    }
    if (threadIdx.x == 0) g_alpha1[n] = red[0] / (float)K_IN;
}

__global__ void prep_w2(const float* __restrict__ w2) {
    __shared__ float a2[N_C];
    int c = threadIdx.x >> 5, l = threadIdx.x & 31;
    if (c < N_C) {
        float s = 0.f;
        for (int j = l; j < N_H; j += 32) s += fabsf(w2[c * N_H + j]);
        #pragma unroll
        for (int o = 16; o; o >>= 1) s += __shfl_down_sync(0xffffffffu, s, o);
        if (l == 0) a2[c] = s / (float)N_H;
    }
    __syncthreads();
    for (int idx = threadIdx.x; idx < N_C * N_H; idx += blockDim.x) {
        g_s2a[idx] = a2[idx / N_H] * signf(w2[idx]);
    }
}

// ---------------- GEMM1: d[B, H] = x[B, K] @ S1t[K, H] ----------------------
// 128x128 tile, BK=16, 256 threads, 8x8 per thread via packed f32x2 FMA.
__global__ __launch_bounds__(256, 2) void gemm1(const float* __restrict__ x) {
    __shared__ float As[BK][BM + 4];
    __shared__ float Bs[BK][BN];

    const int bn = blockIdx.x * BN;   // fast index over N -> A tiles reused in L2
    const int bm = blockIdx.y * BM;
    const int tid = threadIdx.x;
    const int tx = tid & 15, ty = tid >> 4;

    unsigned long long acc[8][4];
    #pragma unroll
    for (int i = 0; i < 8; i++)
        #pragma unroll
        for (int j = 0; j < 4; j++) acc[i][j] = 0ull;

    const int a_row = tid >> 1;            // 0..127
    const int a_k   = (tid & 1) * 8;       // k offset within tile: 0 or 8
    const int b_r   = tid >> 5;            // 0..7
    const int b_c   = (tid & 31) * 4;      // 0..124

    for (int k0 = 0; k0 < K_IN; k0 += BK) {
        float4 av0 = *(const float4*)(x + (size_t)(bm + a_row) * K_IN + k0 + a_k);
        float4 av1 = *(const float4*)(x + (size_t)(bm + a_row) * K_IN + k0 + a_k + 4);
        float4 bv0 = *(const float4*)(g_S1t + (size_t)(k0 + b_r) * N_H + bn + b_c);
        float4 bv1 = *(const float4*)(g_S1t + (size_t)(k0 + b_r + 8) * N_H + bn + b_c);

        As[a_k + 0][a_row] = av0.x;  As[a_k + 1][a_row] = av0.y;
        As[a_k + 2][a_row] = av0.z;  As[a_k + 3][a_row] = av0.w;
        As[a_k + 4][a_row] = av1.x;  As[a_k + 5][a_row] = av1.y;
        As[a_k + 6][a_row] = av1.z;  As[a_k + 7][a_row] = av1.w;
        *(float4*)&Bs[b_r    ][b_c] = bv0;
        *(float4*)&Bs[b_r + 8][b_c] = bv1;
        __syncthreads();

        #pragma unroll
        for (int k = 0; k < BK; k++) {
            float4 a0 = *(const float4*)&As[k][ty * 4];
            float4 a1 = *(const float4*)&As[k][64 + ty * 4];
            float4 b0 = *(const float4*)&Bs[k][tx * 4];
            float4 b1 = *(const float4*)&Bs[k][64 + tx * 4];
            unsigned long long bp[4] = {pk2(b0.x, b0.y), pk2(b0.z, b0.w),
                                        pk2(b1.x, b1.y), pk2(b1.z, b1.w)};
            float ar[8] = {a0.x, a0.y, a0.z, a0.w, a1.x, a1.y, a1.z, a1.w};
            #pragma unroll
            for (int i = 0; i < 8; i++) {
                unsigned long long ap = pk2(ar[i], ar[i]);
                fma2(acc[i][0], ap, bp[0]);
                fma2(acc[i][1], ap, bp[1]);
                fma2(acc[i][2], ap, bp[2]);
                fma2(acc[i][3], ap, bp[3]);
            }
        }
        __syncthreads();
    }

    #pragma unroll
    for (int i = 0; i < 8; i++) {
        int gr = bm + ((i < 4) ? (ty * 4 + i) : (64 + ty * 4 + (i - 4)));
        float2 p0 = upk(acc[i][0]), p1 = upk(acc[i][1]);
        float2 p2 = upk(acc[i][2]), p3 = upk(acc[i][3]);
        float4 o0 = {p0.x, p0.y, p1.x, p1.y};
        float4 o1 = {p2.x, p2.y, p3.x, p3.y};
        *(float4*)(g_d + (size_t)gr * N_H + bn + tx * 4)      = o0;
        *(float4*)(g_d + (size_t)gr * N_H + bn + 64 + tx * 4) = o1;
    }
}

// ---------------- BN statistics (deterministic two-stage reduction) ---------
__global__ void stats_partial() {
    int col = blockIdx.x * 256 + threadIdx.x;   // grid.x = 4
    int rbase = blockIdx.y * 256;               // grid.y = 256
    float s = 0.f, ss = 0.f;
    #pragma unroll 4
    for (int r = 0; r < 256; r++) {
        float v = g_d[(size_t)(rbase + r) * N_H + col];
        s += v;
        ss = fmaf(v, v, ss);
    }
    g_psum[blockIdx.y * N_H + col] = s;
    g_psq [blockIdx.y * N_H + col] = ss;
}

__global__ void stats_final(const float* __restrict__ gamma,
                            const float* __restrict__ beta) {
    int j = blockIdx.x * 256 + threadIdx.x;     // grid.x = 4
    float s = 0.f, ss = 0.f;
    for (int p = 0; p < 256; p++) {             // fixed order -> deterministic
        s  += g_psum[p * N_H + j];
        ss += g_psq [p * N_H + j];
    }
    float inv = 1.f / (float)B_SZ;
    float mu  = s * inv;
    float var = ss * inv - mu * mu;             // var of d
    float a1  = g_alpha1[j];
    float r   = rsqrtf(a1 * a1 * var + BN_EPS); // h = a1*d, var_h = a1^2 var_d
    float c1  = gamma[j] * a1 * r;
    float c0  = beta[j] - c1 * mu;
    g_c1[j] = c1;
    g_c0[j] = c0;
}

// ---------------- fused sign + GEMM2 (warp per row) -------------------------
__global__ __launch_bounds__(256) void final_k(float* __restrict__ out) {
    __shared__ float s2[N_C][N_H];      // 40 KB
    __shared__ float c1s[N_H];          // 4 KB
    __shared__ float c0s[N_H];          // 4 KB
    for (int i = threadIdx.x; i < N_C * N_H; i += 256) ((float*)s2)[i] = g_s2a[i];
    for (int i = threadIdx.x; i < N_H; i += 256) {
        c1s[i] = g_c1[i];
        c0s[i] = g_c0[i];
    }
    __syncthreads();

    int w = threadIdx.x >> 5, l = threadIdx.x & 31;
    int row = blockIdx.x * 8 + w;
    const float* dr = g_d + (size_t)row * N_H;

    float acc[N_C];
    #pragma unroll
    for (int c = 0; c < N_C; c++) acc[c] = 0.f;

    for (int g = 0; g < 32; g++) {
        int col = g * 32 + l;
        float v = dr[col];
        float s = c1s[col] * v + c0s[col];
        float a = (s > 0.f) ? 1.f : ((s < 0.f) ? -1.f : 0.f);
        #pragma unroll
        for (int c = 0; c < N_C; c++) acc[c] = fmaf(a, s2[c][col], acc[c]);
    }
    #pragma unroll
    for (int c = 0; c < N_C; c++) {
        float v = acc[c];
        #pragma unroll
        for (int o = 16; o; o >>= 1) v += __shfl_down_sync(0xffffffffu, v, o);
        if (l == 0) out[(size_t)row * N_C + c] = v;
    }
}

// ---------------- launch -----------------------------------------------------
extern "C" void kernel_launch(void* const* d_in, const int* in_sizes, int n_in,
                              void* d_out, int out_size) {
    const float* x     = (const float*)d_in[0];
    const float* w1    = (const float*)d_in[1];
    const float* w2    = (const float*)d_in[2];
    const float* gamma = (const float*)d_in[3];
    const float* beta  = (const float*)d_in[4];
    float* out = (float*)d_out;

    prep_w1<<<N_H, 128>>>(w1);
    prep_w2<<<1, 320>>>(w2);
    gemm1<<<dim3(N_H / BN, B_SZ / BM), 256>>>(x);
    stats_partial<<<dim3(4, 256), 256>>>();
    stats_final<<<4, 256>>>(gamma, beta);
    final_k<<<B_SZ / 8, 256>>>(out);
}

// round 4
// speedup vs baseline: 1.9092x; 1.9092x over previous
#include <cuda_runtime.h>
#include <cuda_fp16.h>
#include <cstdint>

#define B_SZ 65536
#define K_IN 784
#define N_H  1024
#define N_C  10
#define BN_EPS 1e-5f

#define BM 128
#define BN 128
#define BK 32
#define KPAD 1600
#define NCHUNK (KPAD / BK)        // 50
#define APITCH 40                 // halves per smem row (32 + 8 pad)

// ---------------- scratch (device globals; no runtime allocation) ----------
__device__ __half g_Ah[(size_t)B_SZ * KPAD];   // [B, 1600] = hi | lo | 0-pad
__device__ __half g_Bh[(size_t)N_H * KPAD];    // [H, 1600] = sign | sign | 0-pad
__device__ float  g_alpha1[N_H];
__device__ float  g_s2a[N_C * N_H];            // alpha2[c] * sign(w2[c][j])
__device__ float  g_d[(size_t)B_SZ * N_H];     // d = x @ sign(w1)^T (fp32)
__device__ float  g_psum[256 * N_H];
__device__ float  g_psq [256 * N_H];
__device__ float  g_c1[N_H];
__device__ float  g_c0[N_H];

// ---------------- PTX helpers (baseline ISA only) ----------------------------
__device__ __forceinline__ uint32_t smem_u32(const void* p) {
    uint32_t a;
    asm("{ .reg .u64 t; cvta.to.shared.u64 t, %1; cvt.u32.u64 %0, t; }"
        : "=r"(a) : "l"(p));
    return a;
}
#define CP16(sm, gm) \
    asm volatile("cp.async.cg.shared.global [%0], [%1], 16;" :: "r"(sm), "l"(gm))

__device__ __forceinline__ void ldsm4(uint32_t* r, uint32_t addr) {
    asm volatile("ldmatrix.sync.aligned.m8n8.x4.shared.b16 {%0,%1,%2,%3}, [%4];"
                 : "=r"(r[0]), "=r"(r[1]), "=r"(r[2]), "=r"(r[3]) : "r"(addr));
}
__device__ __forceinline__ void mma16816(float* d, const uint32_t* a,
                                         const uint32_t* b) {
    asm volatile(
        "mma.sync.aligned.m16n8k16.row.col.f32.f16.f16.f32 "
        "{%0,%1,%2,%3}, {%4,%5,%6,%7}, {%8,%9}, {%0,%1,%2,%3};"
        : "+f"(d[0]), "+f"(d[1]), "+f"(d[2]), "+f"(d[3])
        : "r"(a[0]), "r"(a[1]), "r"(a[2]), "r"(a[3]), "r"(b[0]), "r"(b[1]));
}

__device__ __forceinline__ float signf(float w) {
    return (w > 0.f) ? 1.f : ((w < 0.f) ? -1.f : 0.f);
}

// ---------------- x -> (hi, lo) fp16 split ----------------------------------
__global__ void convert_x(const float* __restrict__ x) {
    size_t i = (size_t)blockIdx.x * 256 + threadIdx.x;   // over B*196 float4s
    size_t row = i / 196, kq = i % 196;
    float4 v = ((const float4*)x)[row * 196 + kq];
    __half h0 = __float2half(v.x), h1 = __float2half(v.y);
    __half h2 = __float2half(v.z), h3 = __float2half(v.w);
    __half l0 = __float2half(v.x - __half2float(h0));
    __half l1 = __float2half(v.y - __half2float(h1));
    __half l2 = __float2half(v.z - __half2float(h2));
    __half l3 = __float2half(v.w - __half2float(h3));
    __half* base = g_Ah + row * KPAD;
    *(__half2*)(base + kq * 4)           = __halves2half2(h0, h1);
    *(__half2*)(base + kq * 4 + 2)       = __halves2half2(h2, h3);
    *(__half2*)(base + 784 + kq * 4)     = __halves2half2(l0, l1);
    *(__half2*)(base + 784 + kq * 4 + 2) = __halves2half2(l2, l3);
    if (kq == 0) {
        uint4 z = {0, 0, 0, 0};
        #pragma unroll
        for (int q = 0; q < 4; q++) *(uint4*)(base + 1568 + q * 8) = z;
    }
}

// ---------------- weight prep ------------------------------------------------
__global__ void prep_w1(const float* __restrict__ w1) {
    int n = blockIdx.x;
    const float* row = w1 + n * K_IN;
    __half* brow = g_Bh + (size_t)n * KPAD;
    float s = 0.f;
    for (int k = threadIdx.x; k < K_IN; k += 128) {
        float w = row[k];
        s += fabsf(w);
        __half hs = __float2half(signf(w));
        brow[k] = hs;
        brow[784 + k] = hs;
    }
    if (threadIdx.x < 32) brow[1568 + threadIdx.x] = __float2half(0.f);
    __shared__ float red[128];
    red[threadIdx.x] = s;
    __syncthreads();
    for (int st = 64; st > 0; st >>= 1) {
        if (threadIdx.x < st) red[threadIdx.x] += red[threadIdx.x + st];
        __syncthreads();
    }
    if (threadIdx.x == 0) g_alpha1[n] = red[0] / (float)K_IN;
}

__global__ void prep_w2(const float* __restrict__ w2) {
    __shared__ float a2[N_C];
    int c = threadIdx.x >> 5, l = threadIdx.x & 31;
    if (c < N_C) {
        float s = 0.f;
        for (int j = l; j < N_H; j += 32) s += fabsf(w2[c * N_H + j]);
        #pragma unroll
        for (int o = 16; o; o >>= 1) s += __shfl_down_sync(0xffffffffu, s, o);
        if (l == 0) a2[c] = s / (float)N_H;
    }
    __syncthreads();
    for (int idx = threadIdx.x; idx < N_C * N_H; idx += blockDim.x)
        g_s2a[idx] = a2[idx / N_H] * signf(w2[idx]);
}

// ---------------- HMMA GEMM: d[B, H] = A @ Bh^T ------------------------------
// 128x128 tile, BK=32, 256 threads (8 warps, 2x4), warp tile 64x32.
// cp.async double buffer, padded smem rows (40 halves) -> conflict-free LDSM.
__global__ __launch_bounds__(256, 2) void gemm1_mma() {
    __shared__ __half As[2][BM][APITCH];
    __shared__ __half Bs[2][BN][APITCH];

    const int tid  = threadIdx.x;
    const int lane = tid & 31;
    const int w    = tid >> 5;
    const int wm   = w & 1;          // 0..1 : 64-row slab
    const int wn   = w >> 1;         // 0..3 : 32-col slab
    const int bm   = blockIdx.y * BM;
    const int bn   = blockIdx.x * BN;

    float acc[4][4][4];
    #pragma unroll
    for (int i = 0; i < 4; i++)
        #pragma unroll
        for (int j = 0; j < 4; j++)
            #pragma unroll
            for (int q = 0; q < 4; q++) acc[i][j][q] = 0.f;

    // cp.async addressing: 512 16B ops per tile -> 2 per thread
    const int ld_row = tid >> 1;            // 0..127
    const int ld_ck  = (tid & 1) * 2;       // 16B chunk pair start (0 or 2)

    auto prefetch = [&](int c, int s) {
        const int k0 = c * BK;
        #pragma unroll
        for (int j = 0; j < 2; j++) {
            int ck = ld_ck + j;             // 0..3 : which 16B of the 64B row
            const __half* ga = g_Ah + (size_t)(bm + ld_row) * KPAD + k0 + ck * 8;
            const __half* gb = g_Bh + (size_t)(bn + ld_row) * KPAD + k0 + ck * 8;
            CP16(smem_u32(&As[s][ld_row][ck * 8]), ga);
            CP16(smem_u32(&Bs[s][ld_row][ck * 8]), gb);
        }
    };

    prefetch(0, 0);
    asm volatile("cp.async.commit_group;");

    for (int c = 0; c < NCHUNK; c++) {
        const int s = c & 1;
        if (c + 1 < NCHUNK) {
            prefetch(c + 1, s ^ 1);
            asm volatile("cp.async.commit_group;");
            asm volatile("cp.async.wait_group 1;" ::: "memory");
        } else {
            asm volatile("cp.async.wait_group 0;" ::: "memory");
        }
        __syncthreads();

        #pragma unroll
        for (int h = 0; h < 2; h++) {        // two k16 halves of BK=32
            uint32_t afr[4][4], bfr[4][2];
            #pragma unroll
            for (int mi = 0; mi < 4; mi++) {
                int r = wm * 64 + mi * 16 + (lane & 15);
                int col = h * 16 + (lane >> 4) * 8;
                ldsm4(afr[mi], smem_u32(&As[s][r][col]));
            }
            #pragma unroll
            for (int jp = 0; jp < 2; jp++) { // each covers 2 n-tiles
                int g = lane >> 3, r = lane & 7;
                int n = wn * 32 + jp * 16 + ((g & 2) ? 8 : 0) + r;
                int col = h * 16 + (g & 1) * 8;
                uint32_t rr[4];
                ldsm4(rr, smem_u32(&Bs[s][n][col]));
                bfr[jp * 2 + 0][0] = rr[0]; bfr[jp * 2 + 0][1] = rr[1];
                bfr[jp * 2 + 1][0] = rr[2]; bfr[jp * 2 + 1][1] = rr[3];
            }
            #pragma unroll
            for (int mi = 0; mi < 4; mi++)
                #pragma unroll
                for (int ni = 0; ni < 4; ni++)
                    mma16816(acc[mi][ni], afr[mi], bfr[ni]);
        }
        __syncthreads();
    }

    // epilogue: direct fp32 stores (8B per thread per tile-row, full sectors)
    float* base = g_d + (size_t)(bm + wm * 64) * N_H + bn + wn * 32;
    #pragma unroll
    for (int mi = 0; mi < 4; mi++) {
        #pragma unroll
        for (int ni = 0; ni < 4; ni++) {
            int r0  = mi * 16 + (lane >> 2);
            int col = ni * 8 + (lane & 3) * 2;
            float2 v0 = {acc[mi][ni][0], acc[mi][ni][1]};
            float2 v1 = {acc[mi][ni][2], acc[mi][ni][3]};
            *(float2*)(base + (size_t)r0 * N_H + col)       = v0;
            *(float2*)(base + (size_t)(r0 + 8) * N_H + col) = v1;
        }
    }
}

// ---------------- BN statistics (deterministic two-stage reduction) ---------
__global__ void stats_partial() {
    int col = blockIdx.x * 256 + threadIdx.x;   // grid.x = 4
    int rbase = blockIdx.y * 256;               // grid.y = 256
    float s = 0.f, ss = 0.f;
    #pragma unroll 4
    for (int r = 0; r < 256; r++) {
        float v = g_d[(size_t)(rbase + r) * N_H + col];
        s += v;
        ss = fmaf(v, v, ss);
    }
    g_psum[blockIdx.y * N_H + col] = s;
    g_psq [blockIdx.y * N_H + col] = ss;
}

__global__ void stats_final(const float* __restrict__ gamma,
                            const float* __restrict__ beta) {
    int j = blockIdx.x * 256 + threadIdx.x;
    float s = 0.f, ss = 0.f;
    for (int p = 0; p < 256; p++) {
        s  += g_psum[p * N_H + j];
        ss += g_psq [p * N_H + j];
    }
    float inv = 1.f / (float)B_SZ;
    float mu  = s * inv;
    float var = ss * inv - mu * mu;
    float a1  = g_alpha1[j];
    float r   = rsqrtf(a1 * a1 * var + BN_EPS);
    float c1  = gamma[j] * a1 * r;
    float c0  = beta[j] - c1 * mu;
    g_c1[j] = c1;
    g_c0[j] = c0;
}

// ---------------- fused sign + GEMM2 (warp per row) -------------------------
__global__ __launch_bounds__(256) void final_k(float* __restrict__ out) {
    __shared__ float s2[N_C][N_H];
    __shared__ float c1s[N_H];
    __shared__ float c0s[N_H];
    for (int i = threadIdx.x; i < N_C * N_H; i += 256) ((float*)s2)[i] = g_s2a[i];
    for (int i = threadIdx.x; i < N_H; i += 256) {
        c1s[i] = g_c1[i];
        c0s[i] = g_c0[i];
    }
    __syncthreads();

    int w = threadIdx.x >> 5, l = threadIdx.x & 31;
    int row = blockIdx.x * 8 + w;
    const float* dr = g_d + (size_t)row * N_H;

    float acc[N_C];
    #pragma unroll
    for (int c = 0; c < N_C; c++) acc[c] = 0.f;

    for (int g = 0; g < 32; g++) {
        int col = g * 32 + l;
        float v = dr[col];
        float s = c1s[col] * v + c0s[col];
        float a = (s > 0.f) ? 1.f : ((s < 0.f) ? -1.f : 0.f);
        #pragma unroll
        for (int c = 0; c < N_C; c++) acc[c] = fmaf(a, s2[c][col], acc[c]);
    }
    #pragma unroll
    for (int c = 0; c < N_C; c++) {
        float v = acc[c];
        #pragma unroll
        for (int o = 16; o; o >>= 1) v += __shfl_down_sync(0xffffffffu, v, o);
        if (l == 0) out[(size_t)row * N_C + c] = v;
    }
}

// ---------------- launch -----------------------------------------------------
extern "C" void kernel_launch(void* const* d_in, const int* in_sizes, int n_in,
                              void* d_out, int out_size) {
    const float* x     = (const float*)d_in[0];
    const float* w1    = (const float*)d_in[1];
    const float* w2    = (const float*)d_in[2];
    const float* gamma = (const float*)d_in[3];
    const float* beta  = (const float*)d_in[4];
    float* out = (float*)d_out;

    convert_x<<<(B_SZ * 196) / 256, 256>>>(x);
    prep_w1<<<N_H, 128>>>(w1);
    prep_w2<<<1, 320>>>(w2);
    gemm1_mma<<<dim3(N_H / BN, B_SZ / BM), 256>>>();
    stats_partial<<<dim3(4, 256), 256>>>();
    stats_final<<<4, 256>>>(gamma, beta);
    final_k<<<B_SZ / 8, 256>>>(out);
}

// round 5
// speedup vs baseline: 2.0150x; 1.0555x over previous
#include <cuda_runtime.h>
#include <cuda_fp16.h>
#include <cstdint>

#define B_SZ 65536
#define K_IN 784
#define N_H  1024
#define N_C  10
#define BN_EPS 1e-5f

#define BM 128
#define BN 256
#define BK 32
#define KPAD 1600
#define NCHUNK (KPAD / BK)        // 50
#define APITCH 40                 // halves per smem row (32 + 8 pad)
#define NSTAGE 4

#define A_STAGE_B (BM * APITCH * 2)           // 10240
#define B_STAGE_B (BN * APITCH * 2)           // 20480
#define SMEM_TOTAL (NSTAGE * (A_STAGE_B + B_STAGE_B))   // 122880
#define NMB (B_SZ / BM)                       // 512 m-blocks

// ---------------- scratch (device globals; no runtime allocation) ----------
__device__ __half g_Ah[(size_t)B_SZ * KPAD];   // [B, 1600] = hi | lo | 0-pad
__device__ __half g_Bh[(size_t)N_H * KPAD];    // [H, 1600] = sign | sign | 0-pad
__device__ float  g_alpha1[N_H];
__device__ float  g_s2a[N_C * N_H];            // alpha2[c] * sign(w2[c][j])
__device__ float  g_d[(size_t)B_SZ * N_H];     // d = x @ sign(w1)^T (fp32)
__device__ float  g_psum[NMB * N_H];
__device__ float  g_psq [NMB * N_H];
__device__ float  g_c1[N_H];
__device__ float  g_c0[N_H];

// ---------------- PTX helpers (baseline ISA only) ----------------------------
__device__ __forceinline__ uint32_t smem_u32(const void* p) {
    uint32_t a;
    asm("{ .reg .u64 t; cvta.to.shared.u64 t, %1; cvt.u32.u64 %0, t; }"
        : "=r"(a) : "l"(p));
    return a;
}
#define CP16(sm, gm) \
    asm volatile("cp.async.cg.shared.global [%0], [%1], 16;" :: "r"(sm), "l"(gm))

__device__ __forceinline__ void ldsm4(uint32_t* r, uint32_t addr) {
    asm volatile("ldmatrix.sync.aligned.m8n8.x4.shared.b16 {%0,%1,%2,%3}, [%4];"
                 : "=r"(r[0]), "=r"(r[1]), "=r"(r[2]), "=r"(r[3]) : "r"(addr));
}
__device__ __forceinline__ void mma16816(float* d, const uint32_t* a,
                                         const uint32_t* b) {
    asm volatile(
        "mma.sync.aligned.m16n8k16.row.col.f32.f16.f16.f32 "
        "{%0,%1,%2,%3}, {%4,%5,%6,%7}, {%8,%9}, {%0,%1,%2,%3};"
        : "+f"(d[0]), "+f"(d[1]), "+f"(d[2]), "+f"(d[3])
        : "r"(a[0]), "r"(a[1]), "r"(a[2]), "r"(a[3]), "r"(b[0]), "r"(b[1]));
}

__device__ __forceinline__ float signf(float w) {
    return (w > 0.f) ? 1.f : ((w < 0.f) ? -1.f : 0.f);
}

// ---------------- x -> (hi, lo) fp16 split ----------------------------------
__global__ void convert_x(const float* __restrict__ x) {
    size_t i = (size_t)blockIdx.x * 256 + threadIdx.x;   // over B*196 float4s
    size_t row = i / 196, kq = i % 196;
    float4 v = ((const float4*)x)[row * 196 + kq];
    __half h0 = __float2half(v.x), h1 = __float2half(v.y);
    __half h2 = __float2half(v.z), h3 = __float2half(v.w);
    __half l0 = __float2half(v.x - __half2float(h0));
    __half l1 = __float2half(v.y - __half2float(h1));
    __half l2 = __float2half(v.z - __half2float(h2));
    __half l3 = __float2half(v.w - __half2float(h3));
    __half* base = g_Ah + row * KPAD;
    *(__half2*)(base + kq * 4)           = __halves2half2(h0, h1);
    *(__half2*)(base + kq * 4 + 2)       = __halves2half2(h2, h3);
    *(__half2*)(base + 784 + kq * 4)     = __halves2half2(l0, l1);
    *(__half2*)(base + 784 + kq * 4 + 2) = __halves2half2(l2, l3);
    if (kq == 0) {
        uint4 z = {0, 0, 0, 0};
        #pragma unroll
        for (int q = 0; q < 4; q++) *(uint4*)(base + 1568 + q * 8) = z;
    }
}

// ---------------- weight prep ------------------------------------------------
__global__ void prep_w1(const float* __restrict__ w1) {
    int n = blockIdx.x;
    const float* row = w1 + n * K_IN;
    __half* brow = g_Bh + (size_t)n * KPAD;
    float s = 0.f;
    for (int k = threadIdx.x; k < K_IN; k += 128) {
        float w = row[k];
        s += fabsf(w);
        __half hs = __float2half(signf(w));
        brow[k] = hs;
        brow[784 + k] = hs;
    }
    if (threadIdx.x < 32) brow[1568 + threadIdx.x] = __float2half(0.f);
    __shared__ float red[128];
    red[threadIdx.x] = s;
    __syncthreads();
    for (int st = 64; st > 0; st >>= 1) {
        if (threadIdx.x < st) red[threadIdx.x] += red[threadIdx.x + st];
        __syncthreads();
    }
    if (threadIdx.x == 0) g_alpha1[n] = red[0] / (float)K_IN;
}

__global__ void prep_w2(const float* __restrict__ w2) {
    __shared__ float a2[N_C];
    int c = threadIdx.x >> 5, l = threadIdx.x & 31;
    if (c < N_C) {
        float s = 0.f;
        for (int j = l; j < N_H; j += 32) s += fabsf(w2[c * N_H + j]);
        #pragma unroll
        for (int o = 16; o; o >>= 1) s += __shfl_down_sync(0xffffffffu, s, o);
        if (l == 0) a2[c] = s / (float)N_H;
    }
    __syncthreads();
    for (int idx = threadIdx.x; idx < N_C * N_H; idx += blockDim.x)
        g_s2a[idx] = a2[idx / N_H] * signf(w2[idx]);
}

// ---------------- HMMA GEMM: d[B, H] = A @ Bh^T + fused BN partials ---------
// CTA 128x256, 512 threads (16 warps: 2 m-slabs x 8 n-slabs), warp tile 64x32.
// 4-stage cp.async pipeline, one __syncthreads per chunk.
__global__ __launch_bounds__(512, 1) void gemm1_mma() {
    extern __shared__ char dsm[];
    __half* Abuf = (__half*)dsm;                          // NSTAGE x 128 x 40
    __half* Bbuf = (__half*)(dsm + NSTAGE * A_STAGE_B);   // NSTAGE x 256 x 40

    const int tid  = threadIdx.x;
    const int lane = tid & 31;
    const int w    = tid >> 5;
    const int wm   = w & 1;          // 0..1 : 64-row slab
    const int wn   = w >> 1;         // 0..7 : 32-col slab
    const int bm   = blockIdx.y * BM;
    const int bn   = blockIdx.x * BN;

    float acc[4][4][4];
    #pragma unroll
    for (int i = 0; i < 4; i++)
        #pragma unroll
        for (int j = 0; j < 4; j++)
            #pragma unroll
            for (int q = 0; q < 4; q++) acc[i][j][q] = 0.f;

    // cp.async addressing: A 512 ops (1/thread), B 1024 ops (2/thread)
    const int a_row = tid >> 2;          // 0..127
    const int a_ck  = tid & 3;           // 16B chunk in 64B row

    auto prefetch = [&](int c) {
        if (c < NCHUNK) {
            const int s  = c & (NSTAGE - 1);
            const int k0 = c * BK;
            {
                const __half* ga = g_Ah + (size_t)(bm + a_row) * KPAD + k0 + a_ck * 8;
                CP16(smem_u32(Abuf + s * BM * APITCH + a_row * APITCH + a_ck * 8), ga);
            }
            #pragma unroll
            for (int j = 0; j < 2; j++) {
                int idx = tid + j * 512;
                int r = idx >> 2, ck = idx & 3;
                const __half* gb = g_Bh + (size_t)(bn + r) * KPAD + k0 + ck * 8;
                CP16(smem_u32(Bbuf + s * BN * APITCH + r * APITCH + ck * 8), gb);
            }
        }
        asm volatile("cp.async.commit_group;");
    };

    prefetch(0); prefetch(1); prefetch(2);

    for (int c = 0; c < NCHUNK; c++) {
        const int s = c & (NSTAGE - 1);
        __syncthreads();                 // all warps done with buffer (c+3)&3
        prefetch(c + 3);
        asm volatile("cp.async.wait_group 3;" ::: "memory");
        __syncthreads();                 // stage c visible to all warps

        const __half* As = Abuf + s * BM * APITCH;
        const __half* Bs = Bbuf + s * BN * APITCH;

        #pragma unroll
        for (int h = 0; h < 2; h++) {    // two k16 halves of BK=32
            uint32_t afr[4][4], bfr[4][2];
            #pragma unroll
            for (int mi = 0; mi < 4; mi++) {
                int r = wm * 64 + mi * 16 + (lane & 15);
                int col = h * 16 + (lane >> 4) * 8;
                ldsm4(afr[mi], smem_u32(As + r * APITCH + col));
            }
            #pragma unroll
            for (int jp = 0; jp < 2; jp++) {
                int g = lane >> 3, r = lane & 7;
                int n = wn * 32 + jp * 16 + ((g & 2) ? 8 : 0) + r;
                int col = h * 16 + (g & 1) * 8;
                uint32_t rr[4];
                ldsm4(rr, smem_u32(Bs + n * APITCH + col));
                bfr[jp * 2 + 0][0] = rr[0]; bfr[jp * 2 + 0][1] = rr[1];
                bfr[jp * 2 + 1][0] = rr[2]; bfr[jp * 2 + 1][1] = rr[3];
            }
            #pragma unroll
            for (int mi = 0; mi < 4; mi++)
                #pragma unroll
                for (int ni = 0; ni < 4; ni++)
                    mma16816(acc[mi][ni], afr[mi], bfr[ni]);
        }
    }

    // ---- epilogue 1: store d tile --------------------------------------
    float* base = g_d + (size_t)(bm + wm * 64) * N_H + bn + wn * 32;
    #pragma unroll
    for (int mi = 0; mi < 4; mi++) {
        #pragma unroll
        for (int ni = 0; ni < 4; ni++) {
            int r0  = mi * 16 + (lane >> 2);
            int col = ni * 8 + (lane & 3) * 2;
            float2 v0 = {acc[mi][ni][0], acc[mi][ni][1]};
            float2 v1 = {acc[mi][ni][2], acc[mi][ni][3]};
            *(float2*)(base + (size_t)r0 * N_H + col)       = v0;
            *(float2*)(base + (size_t)(r0 + 8) * N_H + col) = v1;
        }
    }

    // ---- epilogue 2: fused BN partial sums (deterministic) --------------
    // per-thread column partials over its 8 rows, cols = wn*32 + ni*8 + (lane&3)*2 + q
    float cs[8], cq[8];
    #pragma unroll
    for (int ni = 0; ni < 4; ni++) {
        #pragma unroll
        for (int q = 0; q < 2; q++) {
            float s = 0.f, sq = 0.f;
            #pragma unroll
            for (int mi = 0; mi < 4; mi++) {
                float v0 = acc[mi][ni][q], v1 = acc[mi][ni][q + 2];
                s += v0 + v1;
                sq = fmaf(v0, v0, sq);
                sq = fmaf(v1, v1, sq);
            }
            cs[ni * 2 + q] = s;
            cq[ni * 2 + q] = sq;
        }
    }
    // reduce over lanes sharing (lane&3): xor 4, 8, 16
    #pragma unroll
    for (int o = 4; o <= 16; o <<= 1) {
        #pragma unroll
        for (int t = 0; t < 8; t++) {
            cs[t] += __shfl_xor_sync(0xffffffffu, cs[t], o);
            cq[t] += __shfl_xor_sync(0xffffffffu, cq[t], o);
        }
    }
    __syncthreads();                       // pipeline smem no longer needed
    float* sS = (float*)dsm;               // [2][256]
    float* sQ = sS + 512;                  // [2][256]
    if (lane < 4) {
        #pragma unroll
        for (int ni = 0; ni < 4; ni++) {
            #pragma unroll
            for (int q = 0; q < 2; q++) {
                int colL = wn * 32 + ni * 8 + lane * 2 + q;
                sS[wm * 256 + colL] = cs[ni * 2 + q];
                sQ[wm * 256 + colL] = cq[ni * 2 + q];
            }
        }
    }
    __syncthreads();
    if (tid < 256) {
        float s  = sS[tid] + sS[256 + tid];
        float sq = sQ[tid] + sQ[256 + tid];
        g_psum[(size_t)blockIdx.y * N_H + bn + tid] = s;
        g_psq [(size_t)blockIdx.y * N_H + bn + tid] = sq;
    }
}

// ---------------- BN stats finalize (deterministic) --------------------------
__global__ void stats_final(const float* __restrict__ gamma,
                            const float* __restrict__ beta) {
    int j = blockIdx.x * 256 + threadIdx.x;     // grid.x = 4
    float s = 0.f, ss = 0.f;
    for (int p = 0; p < NMB; p++) {             // fixed order -> deterministic
        s  += g_psum[(size_t)p * N_H + j];
        ss += g_psq [(size_t)p * N_H + j];
    }
    float inv = 1.f / (float)B_SZ;
    float mu  = s * inv;
    float var = ss * inv - mu * mu;
    float a1  = g_alpha1[j];
    float r   = rsqrtf(a1 * a1 * var + BN_EPS);
    float c1  = gamma[j] * a1 * r;
    float c0  = beta[j] - c1 * mu;
    g_c1[j] = c1;
    g_c0[j] = c0;
}

// ---------------- fused sign + GEMM2 (warp per row) -------------------------
__global__ __launch_bounds__(256) void final_k(float* __restrict__ out) {
    __shared__ float s2[N_C][N_H];
    __shared__ float c1s[N_H];
    __shared__ float c0s[N_H];
    for (int i = threadIdx.x; i < N_C * N_H; i += 256) ((float*)s2)[i] = g_s2a[i];
    for (int i = threadIdx.x; i < N_H; i += 256) {
        c1s[i] = g_c1[i];
        c0s[i] = g_c0[i];
    }
    __syncthreads();

    int w = threadIdx.x >> 5, l = threadIdx.x & 31;
    int row = blockIdx.x * 8 + w;
    const float* dr = g_d + (size_t)row * N_H;

    float acc[N_C];
    #pragma unroll
    for (int c = 0; c < N_C; c++) acc[c] = 0.f;

    for (int g = 0; g < 32; g++) {
        int col = g * 32 + l;
        float v = dr[col];
        float s = c1s[col] * v + c0s[col];
        float a = (s > 0.f) ? 1.f : ((s < 0.f) ? -1.f : 0.f);
        #pragma unroll
        for (int c = 0; c < N_C; c++) acc[c] = fmaf(a, s2[c][col], acc[c]);
    }
    #pragma unroll
    for (int c = 0; c < N_C; c++) {
        float v = acc[c];
        #pragma unroll
        for (int o = 16; o; o >>= 1) v += __shfl_down_sync(0xffffffffu, v, o);
        if (l == 0) out[(size_t)row * N_C + c] = v;
    }
}

// ---------------- launch -----------------------------------------------------
extern "C" void kernel_launch(void* const* d_in, const int* in_sizes, int n_in,
                              void* d_out, int out_size) {
    const float* x     = (const float*)d_in[0];
    const float* w1    = (const float*)d_in[1];
    const float* w2    = (const float*)d_in[2];
    const float* gamma = (const float*)d_in[3];
    const float* beta  = (const float*)d_in[4];
    float* out = (float*)d_out;

    cudaFuncSetAttribute(gemm1_mma, cudaFuncAttributeMaxDynamicSharedMemorySize,
                         SMEM_TOTAL);

    convert_x<<<(B_SZ * 196) / 256, 256>>>(x);
    prep_w1<<<N_H, 128>>>(w1);
    prep_w2<<<1, 320>>>(w2);
    gemm1_mma<<<dim3(N_H / BN, B_SZ / BM), 512, SMEM_TOTAL>>>();
    stats_final<<<4, 256>>>(gamma, beta);
    final_k<<<B_SZ / 8, 256>>>(out);
}

// round 6
// speedup vs baseline: 2.4198x; 1.2009x over previous
#include <cuda_runtime.h>
#include <cuda_fp16.h>
#include <cstdint>

#define B_SZ 65536
#define K_IN 784
#define N_H  1024
#define N_C  10
#define BN_EPS 1e-5f

#define BM 128
#define BN 256
#define BK 32
#define KPAD 1600
#define NCHUNK (KPAD / BK)        // 50
#define APITCH 40                 // halves per smem row (32 + 8 pad)
#define NSTAGE 5

#define A_STAGE_B (BM * APITCH * 2)           // 10240
#define B_STAGE_B (BN * APITCH * 2)           // 20480
#define SMEM_TOTAL (NSTAGE * (A_STAGE_B + B_STAGE_B))   // 153600
#define NMB (B_SZ / BM)                       // 512 m-blocks

// ---------------- scratch (device globals; no runtime allocation) ----------
__device__ __half g_Ah[(size_t)B_SZ * KPAD];   // [B, 1600] = hi | lo | 0-pad
__device__ __half g_Bh[(size_t)N_H * KPAD];    // [H, 1600] = sign | sign | 0-pad
__device__ float  g_alpha1[N_H];
__device__ float  g_s2a[N_C * N_H];            // alpha2[c] * sign(w2[c][j])
__device__ float  g_d[(size_t)B_SZ * N_H];     // d = x @ sign(w1)^T (fp32)
__device__ float  g_psum[NMB * N_H];
__device__ float  g_psq [NMB * N_H];
__device__ float  g_c1[N_H];
__device__ float  g_c0[N_H];

// ---------------- PTX helpers (baseline ISA only) ----------------------------
__device__ __forceinline__ uint32_t smem_u32(const void* p) {
    uint32_t a;
    asm("{ .reg .u64 t; cvta.to.shared.u64 t, %1; cvt.u32.u64 %0, t; }"
        : "=r"(a) : "l"(p));
    return a;
}
#define CP16(sm, gm) \
    asm volatile("cp.async.cg.shared.global [%0], [%1], 16;" :: "r"(sm), "l"(gm))

__device__ __forceinline__ void ldsm4(uint32_t* r, uint32_t addr) {
    asm volatile("ldmatrix.sync.aligned.m8n8.x4.shared.b16 {%0,%1,%2,%3}, [%4];"
                 : "=r"(r[0]), "=r"(r[1]), "=r"(r[2]), "=r"(r[3]) : "r"(addr));
}
__device__ __forceinline__ void mma16816(float* d, const uint32_t* a,
                                         const uint32_t* b) {
    asm volatile(
        "mma.sync.aligned.m16n8k16.row.col.f32.f16.f16.f32 "
        "{%0,%1,%2,%3}, {%4,%5,%6,%7}, {%8,%9}, {%0,%1,%2,%3};"
        : "+f"(d[0]), "+f"(d[1]), "+f"(d[2]), "+f"(d[3])
        : "r"(a[0]), "r"(a[1]), "r"(a[2]), "r"(a[3]), "r"(b[0]), "r"(b[1]));
}

__device__ __forceinline__ float signf(float w) {
    return (w > 0.f) ? 1.f : ((w < 0.f) ? -1.f : 0.f);
}

// ---------------- x -> (hi, lo) fp16 split ----------------------------------
__global__ void convert_x(const float* __restrict__ x) {
    size_t i = (size_t)blockIdx.x * 256 + threadIdx.x;   // over B*196 float4s
    size_t row = i / 196, kq = i % 196;
    float4 v = ((const float4*)x)[row * 196 + kq];
    __half h0 = __float2half(v.x), h1 = __float2half(v.y);
    __half h2 = __float2half(v.z), h3 = __float2half(v.w);
    __half l0 = __float2half(v.x - __half2float(h0));
    __half l1 = __float2half(v.y - __half2float(h1));
    __half l2 = __float2half(v.z - __half2float(h2));
    __half l3 = __float2half(v.w - __half2float(h3));
    __half* base = g_Ah + row * KPAD;
    *(__half2*)(base + kq * 4)           = __halves2half2(h0, h1);
    *(__half2*)(base + kq * 4 + 2)       = __halves2half2(h2, h3);
    *(__half2*)(base + 784 + kq * 4)     = __halves2half2(l0, l1);
    *(__half2*)(base + 784 + kq * 4 + 2) = __halves2half2(l2, l3);
    if (kq == 0) {
        uint4 z = {0, 0, 0, 0};
        #pragma unroll
        for (int q = 0; q < 4; q++) *(uint4*)(base + 1568 + q * 8) = z;
    }
}

// ---------------- weight prep ------------------------------------------------
__global__ void prep_w1(const float* __restrict__ w1) {
    int n = blockIdx.x;
    const float* row = w1 + n * K_IN;
    __half* brow = g_Bh + (size_t)n * KPAD;
    float s = 0.f;
    for (int k = threadIdx.x; k < K_IN; k += 128) {
        float w = row[k];
        s += fabsf(w);
        __half hs = __float2half(signf(w));
        brow[k] = hs;
        brow[784 + k] = hs;
    }
    if (threadIdx.x < 32) brow[1568 + threadIdx.x] = __float2half(0.f);
    __shared__ float red[128];
    red[threadIdx.x] = s;
    __syncthreads();
    for (int st = 64; st > 0; st >>= 1) {
        if (threadIdx.x < st) red[threadIdx.x] += red[threadIdx.x + st];
        __syncthreads();
    }
    if (threadIdx.x == 0) g_alpha1[n] = red[0] / (float)K_IN;
}

__global__ void prep_w2(const float* __restrict__ w2) {
    __shared__ float a2[N_C];
    int c = threadIdx.x >> 5, l = threadIdx.x & 31;
    if (c < N_C) {
        float s = 0.f;
        for (int j = l; j < N_H; j += 32) s += fabsf(w2[c * N_H + j]);
        #pragma unroll
        for (int o = 16; o; o >>= 1) s += __shfl_down_sync(0xffffffffu, s, o);
        if (l == 0) a2[c] = s / (float)N_H;
    }
    __syncthreads();
    for (int idx = threadIdx.x; idx < N_C * N_H; idx += blockDim.x)
        g_s2a[idx] = a2[idx / N_H] * signf(w2[idx]);
}

// ---------------- HMMA GEMM: d[B, H] = A @ Bh^T + fused BN partials ---------
// CTA 128x256, 512 threads (16 warps: 2 m-slabs x 8 n-slabs), warp tile 64x32.
// 5-stage cp.async pipeline, ONE __syncthreads per chunk, hoisted LDSM addrs.
__global__ __launch_bounds__(512, 1) void gemm1_mma() {
    extern __shared__ char dsm[];
    __half* Abuf = (__half*)dsm;                          // NSTAGE x 128 x 40
    __half* Bbuf = (__half*)(dsm + NSTAGE * A_STAGE_B);   // NSTAGE x 256 x 40

    const int tid  = threadIdx.x;
    const int lane = tid & 31;
    const int w    = tid >> 5;
    const int wm   = w & 1;          // 0..1 : 64-row slab
    const int wn   = w >> 1;         // 0..7 : 32-col slab
    const int bm   = blockIdx.y * BM;
    const int bn   = blockIdx.x * BN;

    float acc[4][4][4];
    #pragma unroll
    for (int i = 0; i < 4; i++)
        #pragma unroll
        for (int j = 0; j < 4; j++)
            #pragma unroll
            for (int q = 0; q < 4; q++) acc[i][j][q] = 0.f;

    // hoisted LDSM base addresses (stage 0, h = 0)
    uint32_t aAddr[4], bAddr[2];
    #pragma unroll
    for (int mi = 0; mi < 4; mi++)
        aAddr[mi] = smem_u32(Abuf + (wm * 64 + mi * 16 + (lane & 15)) * APITCH
                             + (lane >> 4) * 8);
    {
        int g = lane >> 3, r = lane & 7;
        #pragma unroll
        for (int jp = 0; jp < 2; jp++)
            bAddr[jp] = smem_u32(Bbuf + (wn * 32 + jp * 16 + ((g & 2) ? 8 : 0) + r)
                                 * APITCH + (g & 1) * 8);
    }

    // cp.async addressing: A 512 ops (1/thread), B 1024 ops (2/thread)
    const int a_row = tid >> 2;
    const int a_ck  = tid & 3;
    const uint32_t cpA = smem_u32(Abuf + a_row * APITCH + a_ck * 8);
    const int b_r0 = tid >> 2,          b_ck0 = tid & 3;
    const int b_r1 = (tid + 512) >> 2,  b_ck1 = tid & 3;
    const uint32_t cpB0 = smem_u32(Bbuf + b_r0 * APITCH + b_ck0 * 8);
    const uint32_t cpB1 = smem_u32(Bbuf + b_r1 * APITCH + b_ck1 * 8);
    const __half* gA = g_Ah + (size_t)(bm + a_row) * KPAD + a_ck * 8;
    const __half* gB0 = g_Bh + (size_t)(bn + b_r0) * KPAD + b_ck0 * 8;
    const __half* gB1 = g_Bh + (size_t)(bn + b_r1) * KPAD + b_ck1 * 8;

    auto prefetch = [&](int c) {
        if (c < NCHUNK) {
            const uint32_t sA = (uint32_t)(c % NSTAGE) * A_STAGE_B;
            const uint32_t sB = (uint32_t)(c % NSTAGE) * B_STAGE_B;
            const int k0 = c * BK;
            CP16(cpA + sA, gA + k0);
            CP16(cpB0 + sB, gB0 + k0);
            CP16(cpB1 + sB, gB1 + k0);
        }
        asm volatile("cp.async.commit_group;");
    };

    prefetch(0); prefetch(1); prefetch(2); prefetch(3);

    #pragma unroll 5
    for (int c = 0; c < NCHUNK; c++) {
        asm volatile("cp.async.wait_group %0;" :: "n"(NSTAGE - 2) : "memory");
        __syncthreads();
        prefetch(c + NSTAGE - 1);

        const uint32_t sA = (uint32_t)(c % NSTAGE) * A_STAGE_B;
        const uint32_t sB = (uint32_t)(c % NSTAGE) * B_STAGE_B;

        // B fragments for both k16 halves up front
        uint32_t bfr[2][4][2];
        #pragma unroll
        for (int h = 0; h < 2; h++) {
            #pragma unroll
            for (int jp = 0; jp < 2; jp++) {
                uint32_t rr[4];
                ldsm4(rr, bAddr[jp] + sB + h * 32);
                bfr[h][jp * 2 + 0][0] = rr[0]; bfr[h][jp * 2 + 0][1] = rr[1];
                bfr[h][jp * 2 + 1][0] = rr[2]; bfr[h][jp * 2 + 1][1] = rr[3];
            }
        }
        uint32_t afr[4][4];
        #pragma unroll
        for (int mi = 0; mi < 4; mi++) ldsm4(afr[mi], aAddr[mi] + sA);
        #pragma unroll
        for (int mi = 0; mi < 4; mi++)
            #pragma unroll
            for (int ni = 0; ni < 4; ni++)
                mma16816(acc[mi][ni], afr[mi], bfr[0][ni]);
        #pragma unroll
        for (int mi = 0; mi < 4; mi++) ldsm4(afr[mi], aAddr[mi] + sA + 32);
        #pragma unroll
        for (int mi = 0; mi < 4; mi++)
            #pragma unroll
            for (int ni = 0; ni < 4; ni++)
                mma16816(acc[mi][ni], afr[mi], bfr[1][ni]);
    }

    // ---- epilogue 1: store d tile --------------------------------------
    float* base = g_d + (size_t)(bm + wm * 64) * N_H + bn + wn * 32;
    #pragma unroll
    for (int mi = 0; mi < 4; mi++) {
        #pragma unroll
        for (int ni = 0; ni < 4; ni++) {
            int r0  = mi * 16 + (lane >> 2);
            int col = ni * 8 + (lane & 3) * 2;
            float2 v0 = {acc[mi][ni][0], acc[mi][ni][1]};
            float2 v1 = {acc[mi][ni][2], acc[mi][ni][3]};
            *(float2*)(base + (size_t)r0 * N_H + col)       = v0;
            *(float2*)(base + (size_t)(r0 + 8) * N_H + col) = v1;
        }
    }

    // ---- epilogue 2: fused BN partial sums (deterministic) --------------
    float cs[8], cq[8];
    #pragma unroll
    for (int ni = 0; ni < 4; ni++) {
        #pragma unroll
        for (int q = 0; q < 2; q++) {
            float s = 0.f, sq = 0.f;
            #pragma unroll
            for (int mi = 0; mi < 4; mi++) {
                float v0 = acc[mi][ni][q], v1 = acc[mi][ni][q + 2];
                s += v0 + v1;
                sq = fmaf(v0, v0, sq);
                sq = fmaf(v1, v1, sq);
            }
            cs[ni * 2 + q] = s;
            cq[ni * 2 + q] = sq;
        }
    }
    #pragma unroll
    for (int o = 4; o <= 16; o <<= 1) {
        #pragma unroll
        for (int t = 0; t < 8; t++) {
            cs[t] += __shfl_xor_sync(0xffffffffu, cs[t], o);
            cq[t] += __shfl_xor_sync(0xffffffffu, cq[t], o);
        }
    }
    __syncthreads();                       // pipeline smem no longer needed
    float* sS = (float*)dsm;               // [2][256]
    float* sQ = sS + 512;                  // [2][256]
    if (lane < 4) {
        #pragma unroll
        for (int ni = 0; ni < 4; ni++) {
            #pragma unroll
            for (int q = 0; q < 2; q++) {
                int colL = wn * 32 + ni * 8 + lane * 2 + q;
                sS[wm * 256 + colL] = cs[ni * 2 + q];
                sQ[wm * 256 + colL] = cq[ni * 2 + q];
            }
        }
    }
    __syncthreads();
    if (tid < 256) {
        float s  = sS[tid] + sS[256 + tid];
        float sq = sQ[tid] + sQ[256 + tid];
        g_psum[(size_t)blockIdx.y * N_H + bn + tid] = s;
        g_psq [(size_t)blockIdx.y * N_H + bn + tid] = sq;
    }
}

// ---------------- BN stats finalize (deterministic) --------------------------
__global__ void stats_final(const float* __restrict__ gamma,
                            const float* __restrict__ beta) {
    int j = blockIdx.x * 256 + threadIdx.x;     // grid.x = 4
    float s = 0.f, ss = 0.f;
    for (int p = 0; p < NMB; p++) {             // fixed order -> deterministic
        s  += g_psum[(size_t)p * N_H + j];
        ss += g_psq [(size_t)p * N_H + j];
    }
    float inv = 1.f / (float)B_SZ;
    float mu  = s * inv;
    float var = ss * inv - mu * mu;
    float a1  = g_alpha1[j];
    float r   = rsqrtf(a1 * a1 * var + BN_EPS);
    float c1  = gamma[j] * a1 * r;
    float c0  = beta[j] - c1 * mu;
    g_c1[j] = c1;
    g_c0[j] = c0;
}

// ---------------- fused sign + GEMM2 (warp per row) -------------------------
__global__ __launch_bounds__(256) void final_k(float* __restrict__ out) {
    __shared__ float s2[N_C][N_H];
    __shared__ float c1s[N_H];
    __shared__ float c0s[N_H];
    for (int i = threadIdx.x; i < N_C * N_H; i += 256) ((float*)s2)[i] = g_s2a[i];
    for (int i = threadIdx.x; i < N_H; i += 256) {
        c1s[i] = g_c1[i];
        c0s[i] = g_c0[i];
    }
    __syncthreads();

    int w = threadIdx.x >> 5, l = threadIdx.x & 31;
    int row = blockIdx.x * 8 + w;
    const float* dr = g_d + (size_t)row * N_H;

    float acc[N_C];
    #pragma unroll
    for (int c = 0; c < N_C; c++) acc[c] = 0.f;

    for (int g = 0; g < 32; g++) {
        int col = g * 32 + l;
        float v = dr[col];
        float s = c1s[col] * v + c0s[col];
        float a = (s > 0.f) ? 1.f : ((s < 0.f) ? -1.f : 0.f);
        #pragma unroll
        for (int c = 0; c < N_C; c++) acc[c] = fmaf(a, s2[c][col], acc[c]);
    }
    #pragma unroll
    for (int c = 0; c < N_C; c++) {
        float v = acc[c];
        #pragma unroll
        for (int o = 16; o; o >>= 1) v += __shfl_down_sync(0xffffffffu, v, o);
        if (l == 0) out[(size_t)row * N_C + c] = v;
    }
}

// ---------------- launch -----------------------------------------------------
extern "C" void kernel_launch(void* const* d_in, const int* in_sizes, int n_in,
                              void* d_out, int out_size) {
    const float* x     = (const float*)d_in[0];
    const float* w1    = (const float*)d_in[1];
    const float* w2    = (const float*)d_in[2];
    const float* gamma = (const float*)d_in[3];
    const float* beta  = (const float*)d_in[4];
    float* out = (float*)d_out;

    cudaFuncSetAttribute(gemm1_mma, cudaFuncAttributeMaxDynamicSharedMemorySize,
                         SMEM_TOTAL);

    convert_x<<<(B_SZ * 196) / 256, 256>>>(x);
    prep_w1<<<N_H, 128>>>(w1);
    prep_w2<<<1, 320>>>(w2);
    gemm1_mma<<<dim3(N_H / BN, B_SZ / BM), 512, SMEM_TOTAL>>>();
    stats_final<<<4, 256>>>(gamma, beta);
    final_k<<<B_SZ / 8, 256>>>(out);
}